// round 3
// baseline (speedup 1.0000x reference)
#include <cuda_runtime.h>
#include <math.h>

#define Bn 16
#define Hn 512
#define Wn 512
#define C1 16
#define C2 18
#define TW 32
#define TH 32
#define HALO 34

typedef unsigned long long u64;

// 256 MB scratch for conv1 output (B, C1, H, W)
__device__ float g_feat[(size_t)Bn * C1 * Hn * Wn];

// ---- f32x2 packed helpers (sm_100+) --------------------------------------
__device__ __forceinline__ u64 pack2(float lo, float hi) {
    u64 r;
    asm("mov.b64 %0, {%1, %2};" : "=l"(r) : "f"(lo), "f"(hi));
    return r;
}
__device__ __forceinline__ void unpack2(u64 v, float& lo, float& hi) {
    asm("mov.b64 {%0, %1}, %2;" : "=f"(lo), "=f"(hi) : "l"(v));
}
__device__ __forceinline__ void fma2(u64& d, u64 a, u64 b) {
    asm("fma.rn.f32x2 %0, %1, %2, %0;" : "+l"(d) : "l"(a), "l"(b));
}

// ---------------------------------------------------------------------------
// Kernel 1: conv1 (3->16, 3x3, pad 1) + bias + exact GELU -> g_feat
// Vertical pixel pair per thread, packed f32x2 FMA, duplicated weights in
// smem so LDS.128 yields two (w,w) packed operands.
// ---------------------------------------------------------------------------
__global__ __launch_bounds__(256) void conv1_gelu_kernel(
        const float* __restrict__ wind,
        const float* __restrict__ topo,
        const float* __restrict__ w1,
        const float* __restrict__ b1) {
    // per oc: 27 taps duplicated (54 floats) + 2 pad = 56 floats (224B, 16B aligned)
    __shared__ float wsd[C1 * 56];
    __shared__ float bs[C1];
    int tid = threadIdx.x;
    for (int i = tid; i < C1 * 28; i += 256) {
        int j  = i % 28;
        int oc = i / 28;
        float v = (j < 27) ? w1[oc * 27 + j] : 0.0f;
        wsd[oc * 56 + 2 * j]     = v;
        wsd[oc * 56 + 2 * j + 1] = v;
    }
    if (tid < C1) bs[tid] = b1[tid];
    __syncthreads();

    int idx = blockIdx.x * blockDim.x + tid;      // [0, B*(H/2)*W)
    int x  = idx % Wn;
    int r  = idx / Wn;
    int y0 = (r % (Hn / 2)) * 2;
    int b  = r / (Hn / 2);

    const float* chp[3] = {
        wind + ((size_t)b * 2 + 0) * Hn * Wn,
        wind + ((size_t)b * 2 + 1) * Hn * Wn,
        topo + (size_t)b * Hn * Wn
    };

    // input rows y0-1 .. y0+2, cols x-1..x+1, 3 channels
    float in[3][4][3];
    #pragma unroll
    for (int i = 0; i < 3; i++) {
        #pragma unroll
        for (int yy = 0; yy < 4; yy++) {
            int gy = y0 - 1 + yy;
            #pragma unroll
            for (int xx = 0; xx < 3; xx++) {
                int gx = x - 1 + xx;
                float v = 0.0f;
                if (gy >= 0 && gy < Hn && gx >= 0 && gx < Wn)
                    v = __ldg(chp[i] + gy * Wn + gx);
                in[i][yy][xx] = v;
            }
        }
    }

    // packed feature pairs, ordered j = i*9 + ky*3 + kx; p[27] = 0 pad
    u64 p[28];
    #pragma unroll
    for (int i = 0; i < 3; i++)
        #pragma unroll
        for (int ky = 0; ky < 3; ky++)
            #pragma unroll
            for (int kx = 0; kx < 3; kx++)
                p[i * 9 + ky * 3 + kx] = pack2(in[i][ky][kx], in[i][ky + 1][kx]);
    p[27] = 0ull;

    const float inv_sqrt2 = 0.70710678118654752440f;
    #pragma unroll
    for (int oc = 0; oc < C1; oc++) {
        u64 acc = pack2(bs[oc], bs[oc]);
        const ulonglong2* wq = (const ulonglong2*)(wsd + oc * 56);
        #pragma unroll
        for (int j2 = 0; j2 < 14; j2++) {
            ulonglong2 q = wq[j2];
            fma2(acc, q.x, p[2 * j2]);
            fma2(acc, q.y, p[2 * j2 + 1]);
        }
        float a0, a1;
        unpack2(acc, a0, a1);
        a0 = 0.5f * a0 * (1.0f + erff(a0 * inv_sqrt2));
        a1 = 0.5f * a1 * (1.0f + erff(a1 * inv_sqrt2));
        size_t base = (((size_t)b * C1 + oc) * Hn + y0) * Wn + x;
        g_feat[base]      = a0;
        g_feat[base + Wn] = a1;
    }
}

// ---------------------------------------------------------------------------
// Bilinear sampling helpers
// ---------------------------------------------------------------------------
__device__ __forceinline__ float samp_point(const float* __restrict__ img,
                                            int yi, int xi) {
    bool valid = (yi >= 0) & (yi < Hn) & (xi >= 0) & (xi < Wn);
    int yc = min(max(yi, 0), Hn - 1);
    int xc = min(max(xi, 0), Wn - 1);
    float v = __ldg(img + yc * Wn + xc);
    return valid ? v : 0.0f;
}

__device__ __forceinline__ float bilinear(const float* __restrict__ img,
                                          float py, float px) {
    float fy = floorf(py), fx = floorf(px);
    float wy = py - fy,    wx = px - fx;
    int yi = (int)fy,      xi = (int)fx;
    float v00 = samp_point(img, yi,     xi);
    float v01 = samp_point(img, yi,     xi + 1);
    float v10 = samp_point(img, yi + 1, xi);
    float v11 = samp_point(img, yi + 1, xi + 1);
    float omy = 1.0f - wy, omx = 1.0f - wx;
    return v00 * omy * omx + v01 * omy * wx + v10 * wy * omx + v11 * wy * wx;
}

// ---------------------------------------------------------------------------
// Kernel 2 (fused): conv2 (16->18, 3x3, pad 1) + bias -> offsets in
// registers (f32x2 packed, dup weights), then deformable bilinear sampling.
// 256 threads, 32x32 tile, 4 consecutive rows per thread.
// ---------------------------------------------------------------------------
__global__ __launch_bounds__(256) void conv2_sample_kernel(
        const float* __restrict__ pm25,
        const float* __restrict__ w2,
        const float* __restrict__ b2,
        const float* __restrict__ wk,
        float* __restrict__ out) {
    extern __shared__ float smem[];
    float* sfeat = smem;                                // C1*34*34
    float* swd   = sfeat + C1 * HALO * HALO;            // C1*C2*20 (dup taps)
    float* sb2   = swd + C1 * C2 * 20;                  // C2
    float* swk   = sb2 + C2;                            // 9

    int tid = threadIdx.x;                              // 256
    int bx0 = blockIdx.x * TW;
    int by0 = blockIdx.y * TH;
    int b   = blockIdx.z;

    // dup-weight staging: per (c,oc): taps 0..8 duplicated + pad (20 floats, 80B)
    for (int i = tid; i < C1 * C2 * 10; i += 256) {
        int t   = i % 10;
        int rem = i / 10;             // c*C2 + oc
        int oc  = rem % C2;
        int c   = rem / C2;
        float v = (t < 9) ? w2[(oc * C1 + c) * 9 + t] : 0.0f;
        swd[rem * 20 + 2 * t]     = v;
        swd[rem * 20 + 2 * t + 1] = v;
    }
    if (tid < C2) sb2[tid] = b2[tid];
    if (tid < 9)  swk[tid] = wk[tid];

    // feat tile load with zero halo (incremental (yy,xx) walk, no per-iter div)
    int yy0 = tid / HALO;
    int xx0 = tid - yy0 * HALO;
    #pragma unroll 1
    for (int c = 0; c < C1; c++) {
        const float* src = g_feat + ((size_t)b * C1 + c) * Hn * Wn;
        float* dst = sfeat + c * HALO * HALO;
        int cyy = yy0, cxx = xx0;
        while (cyy < HALO) {
            int gy = by0 + cyy - 1;
            int gx = bx0 + cxx - 1;
            float v = 0.0f;
            if ((unsigned)gy < Hn && (unsigned)gx < Wn)
                v = __ldg(src + gy * Wn + gx);
            dst[cyy * HALO + cxx] = v;
            // advance by 256 = 7*34 + 18
            cxx += 18; cyy += 7;
            if (cxx >= HALO) { cxx -= HALO; cyy += 1; }
        }
    }
    __syncthreads();

    int tx  = tid & 31;
    int r   = tid >> 5;          // 0..7
    int ylo = 4 * r;             // tile-local output rows ylo..ylo+3

    u64 accA[C2], accB[C2];      // A: rows (ylo, ylo+1); B: rows (ylo+2, ylo+3)
    #pragma unroll
    for (int oc = 0; oc < C2; oc++) {
        u64 bb = pack2(sb2[oc], sb2[oc]);
        accA[oc] = bb;
        accB[oc] = bb;
    }

    #pragma unroll 1
    for (int c = 0; c < C1; c++) {
        const float* fp = sfeat + c * HALO * HALO + ylo * HALO + tx;
        float fl[6][3];
        #pragma unroll
        for (int dy = 0; dy < 6; dy++)
            #pragma unroll
            for (int dx = 0; dx < 3; dx++)
                fl[dy][dx] = fp[dy * HALO + dx];

        u64 pA[9], pB[9];
        #pragma unroll
        for (int ky = 0; ky < 3; ky++)
            #pragma unroll
            for (int kx = 0; kx < 3; kx++) {
                pA[ky * 3 + kx] = pack2(fl[ky][kx],     fl[ky + 1][kx]);
                pB[ky * 3 + kx] = pack2(fl[ky + 2][kx], fl[ky + 3][kx]);
            }

        const float* wbase = swd + c * C2 * 20;
        #pragma unroll
        for (int oc = 0; oc < C2; oc++) {
            const ulonglong2* wq = (const ulonglong2*)(wbase + oc * 20);
            ulonglong2 q0 = wq[0];   // taps 0,1
            ulonglong2 q1 = wq[1];   // taps 2,3
            ulonglong2 q2 = wq[2];   // taps 4,5
            ulonglong2 q3 = wq[3];   // taps 6,7
            u64 w8 = ((const u64*)(wbase + oc * 20))[8];  // tap 8
            fma2(accA[oc], q0.x, pA[0]);  fma2(accB[oc], q0.x, pB[0]);
            fma2(accA[oc], q0.y, pA[1]);  fma2(accB[oc], q0.y, pB[1]);
            fma2(accA[oc], q1.x, pA[2]);  fma2(accB[oc], q1.x, pB[2]);
            fma2(accA[oc], q1.y, pA[3]);  fma2(accB[oc], q1.y, pB[3]);
            fma2(accA[oc], q2.x, pA[4]);  fma2(accB[oc], q2.x, pB[4]);
            fma2(accA[oc], q2.y, pA[5]);  fma2(accB[oc], q2.y, pB[5]);
            fma2(accA[oc], q3.x, pA[6]);  fma2(accB[oc], q3.x, pB[6]);
            fma2(accA[oc], q3.y, pA[7]);  fma2(accB[oc], q3.y, pB[7]);
            fma2(accA[oc], w8,   pA[8]);  fma2(accB[oc], w8,   pB[8]);
        }
    }

    // ---- deformable sampling (4 rows) ----
    const float* img = pm25 + (size_t)b * Hn * Wn;
    int x = bx0 + tx;
    float ybase = (float)(by0 + ylo);
    float xf = (float)x;

    float o0 = 0.0f, o1 = 0.0f, o2 = 0.0f, o3 = 0.0f;
    #pragma unroll
    for (int k = 0; k < 9; k++) {
        float wkv = swk[k];
        if (wkv != 0.0f) {
            float kdy = (float)(k / 3 - 1);
            float kdx = (float)(k % 3 - 1);
            float dy0, dy1, dy2, dy3, dx0, dx1, dx2, dx3;
            unpack2(accA[2 * k],     dy0, dy1);
            unpack2(accB[2 * k],     dy2, dy3);
            unpack2(accA[2 * k + 1], dx0, dx1);
            unpack2(accB[2 * k + 1], dx2, dx3);
            o0 = fmaf(wkv, bilinear(img, ybase + 0.0f + kdy + dy0, xf + kdx + dx0), o0);
            o1 = fmaf(wkv, bilinear(img, ybase + 1.0f + kdy + dy1, xf + kdx + dx1), o1);
            o2 = fmaf(wkv, bilinear(img, ybase + 2.0f + kdy + dy2, xf + kdx + dx2), o2);
            o3 = fmaf(wkv, bilinear(img, ybase + 3.0f + kdy + dy3, xf + kdx + dx3), o3);
        }
    }
    size_t ob = ((size_t)b * Hn + (by0 + ylo)) * Wn + x;
    out[ob]          = o0;
    out[ob + Wn]     = o1;
    out[ob + 2 * Wn] = o2;
    out[ob + 3 * Wn] = o3;
}

// ---------------------------------------------------------------------------
extern "C" void kernel_launch(void* const* d_in, const int* in_sizes, int n_in,
                              void* d_out, int out_size) {
    const float* pm25 = (const float*)d_in[0];
    const float* wind = (const float*)d_in[1];
    const float* topo = (const float*)d_in[2];
    const float* w1   = (const float*)d_in[3];
    const float* b1   = (const float*)d_in[4];
    const float* w2   = (const float*)d_in[5];
    const float* b2   = (const float*)d_in[6];
    const float* wk   = (const float*)d_in[7];
    float* out = (float*)d_out;

    // Kernel 1: conv1 + GELU
    int n1 = Bn * (Hn / 2) * Wn;                  // 2,097,152 threads
    conv1_gelu_kernel<<<n1 / 256, 256>>>(wind, topo, w1, b1);

    // Kernel 2: fused conv2 + sampling
    int smemB = (C1 * HALO * HALO + C1 * C2 * 20 + C2 + 9) * (int)sizeof(float);
    cudaFuncSetAttribute(conv2_sample_kernel,
                         cudaFuncAttributeMaxDynamicSharedMemorySize, smemB);
    dim3 grid(Wn / TW, Hn / TH, Bn);
    conv2_sample_kernel<<<grid, 256, smemB>>>(pm25, w2, b2, wk, out);
}

// round 4
// speedup vs baseline: 1.7174x; 1.7174x over previous
#include <cuda_runtime.h>
#include <math.h>

#define Bn 16
#define Hn 512
#define Wn 512
#define C1 16
#define C2 18
#define TW 32          // K2 tile width
#define THY 16         // K2 tile height
#define HX 34          // TW+2
#define HY 18          // THY+2
#define PLANE (HX*HY)  // 612

typedef unsigned long long u64;

// 256 MB scratch for conv1 output (B, C1, H, W)
__device__ float g_feat[(size_t)Bn * C1 * Hn * Wn];

// ---- f32x2 packed helpers (sm_100+) --------------------------------------
__device__ __forceinline__ u64 pack2(float lo, float hi) {
    u64 r;
    asm("mov.b64 %0, {%1, %2};" : "=l"(r) : "f"(lo), "f"(hi));
    return r;
}
__device__ __forceinline__ void unpack2(u64 v, float& lo, float& hi) {
    asm("mov.b64 {%0, %1}, %2;" : "=f"(lo), "=f"(hi) : "l"(v));
}
__device__ __forceinline__ void fma2(u64& d, u64 a, u64 b) {
    asm("fma.rn.f32x2 %0, %1, %2, %0;" : "+l"(d) : "l"(a), "l"(b));
}

// ---------------------------------------------------------------------------
// Kernel 1: conv1 (3->16, 3x3, pad 1) + bias + exact GELU -> g_feat
// (R2 scalar version: 60 regs, ~48% occ — known good)
// ---------------------------------------------------------------------------
__global__ void conv1_gelu_kernel(const float* __restrict__ wind,
                                  const float* __restrict__ topo,
                                  const float* __restrict__ w1,
                                  const float* __restrict__ b1) {
    __shared__ float ws[C1 * 27];
    __shared__ float bs[C1];
    int tid = threadIdx.x;
    for (int i = tid; i < C1 * 27; i += blockDim.x) ws[i] = w1[i];
    if (tid < C1) bs[tid] = b1[tid];
    __syncthreads();

    int idx = blockIdx.x * blockDim.x + tid;      // [0, B*(H/2)*W)
    int x  = idx % Wn;
    int r  = idx / Wn;
    int y0 = (r % (Hn / 2)) * 2;
    int b  = r / (Hn / 2);

    const float* chp[3] = {
        wind + ((size_t)b * 2 + 0) * Hn * Wn,
        wind + ((size_t)b * 2 + 1) * Hn * Wn,
        topo + (size_t)b * Hn * Wn
    };

    float in[3][4][3];
    #pragma unroll
    for (int i = 0; i < 3; i++) {
        #pragma unroll
        for (int yy = 0; yy < 4; yy++) {
            int gy = y0 - 1 + yy;
            #pragma unroll
            for (int xx = 0; xx < 3; xx++) {
                int gx = x - 1 + xx;
                float v = 0.0f;
                if (gy >= 0 && gy < Hn && gx >= 0 && gx < Wn)
                    v = __ldg(chp[i] + gy * Wn + gx);
                in[i][yy][xx] = v;
            }
        }
    }

    const float inv_sqrt2 = 0.70710678118654752440f;
    #pragma unroll
    for (int oc = 0; oc < C1; oc++) {
        float a0 = bs[oc], a1 = a0;
        #pragma unroll
        for (int i = 0; i < 3; i++) {
            #pragma unroll
            for (int ky = 0; ky < 3; ky++) {
                #pragma unroll
                for (int kx = 0; kx < 3; kx++) {
                    float w = ws[(oc * 3 + i) * 9 + ky * 3 + kx];
                    a0 = fmaf(w, in[i][ky][kx],     a0);
                    a1 = fmaf(w, in[i][ky + 1][kx], a1);
                }
            }
        }
        a0 = 0.5f * a0 * (1.0f + erff(a0 * inv_sqrt2));
        a1 = 0.5f * a1 * (1.0f + erff(a1 * inv_sqrt2));
        size_t base = (((size_t)b * C1 + oc) * Hn + y0) * Wn + x;
        g_feat[base]      = a0;
        g_feat[base + Wn] = a1;
    }
}

// ---------------------------------------------------------------------------
// Bilinear sampling helpers
// ---------------------------------------------------------------------------
__device__ __forceinline__ float samp_point(const float* __restrict__ img,
                                            int yi, int xi) {
    bool valid = (yi >= 0) & (yi < Hn) & (xi >= 0) & (xi < Wn);
    int yc = min(max(yi, 0), Hn - 1);
    int xc = min(max(xi, 0), Wn - 1);
    float v = __ldg(img + yc * Wn + xc);
    return valid ? v : 0.0f;
}

__device__ __forceinline__ float bilinear(const float* __restrict__ img,
                                          float py, float px) {
    float fy = floorf(py), fx = floorf(px);
    float wy = py - fy,    wx = px - fx;
    int yi = (int)fy,      xi = (int)fx;
    float v00 = samp_point(img, yi,     xi);
    float v01 = samp_point(img, yi,     xi + 1);
    float v10 = samp_point(img, yi + 1, xi);
    float v11 = samp_point(img, yi + 1, xi + 1);
    float omy = 1.0f - wy, omx = 1.0f - wx;
    return v00 * omy * omx + v01 * omy * wx + v10 * wy * omx + v11 * wy * wx;
}

// ---------------------------------------------------------------------------
// Kernel 2 (fused): conv2 + bias -> offsets (f32x2, dup weights), then
// deformable bilinear sampling. 256 threads, 32x16 tile, 2 rows/thread,
// max 3 blocks/SM (reg cap 85 -> ~37.5% occupancy).
// ---------------------------------------------------------------------------
__global__ __launch_bounds__(256, 3) void conv2_sample_kernel(
        const float* __restrict__ pm25,
        const float* __restrict__ w2,
        const float* __restrict__ b2,
        const float* __restrict__ wk,
        float* __restrict__ out) {
    extern __shared__ float smem[];
    float* sfeat = smem;                                // C1*PLANE
    float* swd   = sfeat + C1 * PLANE;                  // C1*C2*20 (dup taps)
    float* sb2   = swd + C1 * C2 * 20;                  // C2
    float* swk   = sb2 + C2;                            // 9

    int tid = threadIdx.x;                              // 256
    int bx0 = blockIdx.x * TW;
    int by0 = blockIdx.y * THY;
    int b   = blockIdx.z;

    // dup-weight staging: per (c,oc): taps 0..8 duplicated + pad (20 floats)
    for (int i = tid; i < C1 * C2 * 10; i += 256) {
        int t   = i % 10;
        int rem = i / 10;             // c*C2 + oc
        int oc  = rem % C2;
        int c   = rem / C2;
        float v = (t < 9) ? w2[(oc * C1 + c) * 9 + t] : 0.0f;
        swd[rem * 20 + 2 * t]     = v;
        swd[rem * 20 + 2 * t + 1] = v;
    }
    if (tid < C2) sb2[tid] = b2[tid];
    if (tid < 9)  swk[tid] = wk[tid];

    // feat tile load with zero halo
    {
        int yy0 = tid / HX;
        int xx0 = tid - yy0 * HX;
        #pragma unroll 1
        for (int c = 0; c < C1; c++) {
            const float* src = g_feat + ((size_t)b * C1 + c) * Hn * Wn;
            float* dst = sfeat + c * PLANE;
            int cyy = yy0, cxx = xx0;
            while (cyy < HY) {
                int gy = by0 + cyy - 1;
                int gx = bx0 + cxx - 1;
                float v = 0.0f;
                if ((unsigned)gy < Hn && (unsigned)gx < Wn)
                    v = __ldg(src + gy * Wn + gx);
                dst[cyy * HX + cxx] = v;
                // advance by 256 = 7*34 + 18
                cxx += 18; cyy += 7;
                if (cxx >= HX) { cxx -= HX; cyy += 1; }
            }
        }
    }
    __syncthreads();

    int tx  = tid & 31;
    int r   = tid >> 5;          // 0..7
    int ylo = 2 * r;             // tile-local output rows ylo, ylo+1

    u64 acc[C2];                 // packed (row ylo, row ylo+1)
    #pragma unroll
    for (int oc = 0; oc < C2; oc++)
        acc[oc] = pack2(sb2[oc], sb2[oc]);

    #pragma unroll 1
    for (int c = 0; c < C1; c++) {
        const float* fp = sfeat + c * PLANE + ylo * HX + tx;
        float fl[4][3];
        #pragma unroll
        for (int dy = 0; dy < 4; dy++)
            #pragma unroll
            for (int dx = 0; dx < 3; dx++)
                fl[dy][dx] = fp[dy * HX + dx];

        u64 pA[9];
        #pragma unroll
        for (int ky = 0; ky < 3; ky++)
            #pragma unroll
            for (int kx = 0; kx < 3; kx++)
                pA[ky * 3 + kx] = pack2(fl[ky][kx], fl[ky + 1][kx]);

        const float* wbase = swd + c * C2 * 20;
        #pragma unroll
        for (int oc = 0; oc < C2; oc++) {
            const ulonglong2* wq = (const ulonglong2*)(wbase + oc * 20);
            ulonglong2 q0 = wq[0];   // taps 0,1
            ulonglong2 q1 = wq[1];   // taps 2,3
            ulonglong2 q2 = wq[2];   // taps 4,5
            ulonglong2 q3 = wq[3];   // taps 6,7
            u64 w8 = ((const u64*)(wbase + oc * 20))[8];  // tap 8
            fma2(acc[oc], q0.x, pA[0]);
            fma2(acc[oc], q0.y, pA[1]);
            fma2(acc[oc], q1.x, pA[2]);
            fma2(acc[oc], q1.y, pA[3]);
            fma2(acc[oc], q2.x, pA[4]);
            fma2(acc[oc], q2.y, pA[5]);
            fma2(acc[oc], q3.x, pA[6]);
            fma2(acc[oc], q3.y, pA[7]);
            fma2(acc[oc], w8,   pA[8]);
        }
    }

    // ---- deformable sampling (2 rows) ----
    const float* img = pm25 + (size_t)b * Hn * Wn;
    int x = bx0 + tx;
    float ybase = (float)(by0 + ylo);
    float xf = (float)x;

    float o0 = 0.0f, o1 = 0.0f;
    #pragma unroll
    for (int k = 0; k < 9; k++) {
        float wkv = swk[k];
        if (wkv != 0.0f) {
            float kdy = (float)(k / 3 - 1);
            float kdx = (float)(k % 3 - 1);
            float dy0, dy1, dx0, dx1;
            unpack2(acc[2 * k],     dy0, dy1);
            unpack2(acc[2 * k + 1], dx0, dx1);
            o0 = fmaf(wkv, bilinear(img, ybase + 0.0f + kdy + dy0, xf + kdx + dx0), o0);
            o1 = fmaf(wkv, bilinear(img, ybase + 1.0f + kdy + dy1, xf + kdx + dx1), o1);
        }
    }
    size_t ob = ((size_t)b * Hn + (by0 + ylo)) * Wn + x;
    out[ob]      = o0;
    out[ob + Wn] = o1;
}

// ---------------------------------------------------------------------------
extern "C" void kernel_launch(void* const* d_in, const int* in_sizes, int n_in,
                              void* d_out, int out_size) {
    const float* pm25 = (const float*)d_in[0];
    const float* wind = (const float*)d_in[1];
    const float* topo = (const float*)d_in[2];
    const float* w1   = (const float*)d_in[3];
    const float* b1   = (const float*)d_in[4];
    const float* w2   = (const float*)d_in[5];
    const float* b2   = (const float*)d_in[6];
    const float* wk   = (const float*)d_in[7];
    float* out = (float*)d_out;

    // Kernel 1: conv1 + GELU
    int n1 = Bn * (Hn / 2) * Wn;
    conv1_gelu_kernel<<<n1 / 256, 256>>>(wind, topo, w1, b1);

    // Kernel 2: fused conv2 + sampling
    int smemB = (C1 * PLANE + C1 * C2 * 20 + C2 + 9) * (int)sizeof(float);
    cudaFuncSetAttribute(conv2_sample_kernel,
                         cudaFuncAttributeMaxDynamicSharedMemorySize, smemB);
    dim3 grid(Wn / TW, Hn / THY, Bn);
    conv2_sample_kernel<<<grid, 256, smemB>>>(pm25, w2, b2, wk, out);
}

// round 5
// speedup vs baseline: 2.7491x; 1.6008x over previous
#include <cuda_runtime.h>
#include <math.h>

#define Bn 16
#define Hn 512
#define Wn 512
#define C1 16
#define C2 18
#define TW 32          // K2 tile width
#define THY 16         // K2 tile height
#define HX 34          // TW+2
#define HY 18          // THY+2
#define PLANE (HX*HY)  // 612

typedef unsigned long long u64;

// 256 MB scratch for conv1 output (B, C1, H, W)
__device__ float g_feat[(size_t)Bn * C1 * Hn * Wn];

// ---- f32x2 packed helpers (sm_100+) --------------------------------------
__device__ __forceinline__ u64 pack2(float lo, float hi) {
    u64 r;
    asm("mov.b64 %0, {%1, %2};" : "=l"(r) : "f"(lo), "f"(hi));
    return r;
}
__device__ __forceinline__ void unpack2(u64 v, float& lo, float& hi) {
    asm("mov.b64 {%0, %1}, %2;" : "=f"(lo), "=f"(hi) : "l"(v));
}
__device__ __forceinline__ void fma2(u64& d, u64 a, u64 b) {
    asm("fma.rn.f32x2 %0, %1, %2, %0;" : "+l"(d) : "l"(a), "l"(b));
}

// ---------------------------------------------------------------------------
// Kernel 1: conv1 (3->16, 3x3, pad 1) + bias + exact GELU -> g_feat
// ---------------------------------------------------------------------------
__global__ void conv1_gelu_kernel(const float* __restrict__ wind,
                                  const float* __restrict__ topo,
                                  const float* __restrict__ w1,
                                  const float* __restrict__ b1) {
    __shared__ float ws[C1 * 27];
    __shared__ float bs[C1];
    int tid = threadIdx.x;
    for (int i = tid; i < C1 * 27; i += blockDim.x) ws[i] = w1[i];
    if (tid < C1) bs[tid] = b1[tid];
    __syncthreads();

    int idx = blockIdx.x * blockDim.x + tid;      // [0, B*(H/2)*W)
    int x  = idx % Wn;
    int r  = idx / Wn;
    int y0 = (r % (Hn / 2)) * 2;
    int b  = r / (Hn / 2);

    const float* chp[3] = {
        wind + ((size_t)b * 2 + 0) * Hn * Wn,
        wind + ((size_t)b * 2 + 1) * Hn * Wn,
        topo + (size_t)b * Hn * Wn
    };

    float in[3][4][3];
    #pragma unroll
    for (int i = 0; i < 3; i++) {
        #pragma unroll
        for (int yy = 0; yy < 4; yy++) {
            int gy = y0 - 1 + yy;
            #pragma unroll
            for (int xx = 0; xx < 3; xx++) {
                int gx = x - 1 + xx;
                float v = 0.0f;
                if (gy >= 0 && gy < Hn && gx >= 0 && gx < Wn)
                    v = __ldg(chp[i] + gy * Wn + gx);
                in[i][yy][xx] = v;
            }
        }
    }

    const float inv_sqrt2 = 0.70710678118654752440f;
    #pragma unroll
    for (int oc = 0; oc < C1; oc++) {
        float a0 = bs[oc], a1 = a0;
        #pragma unroll
        for (int i = 0; i < 3; i++) {
            #pragma unroll
            for (int ky = 0; ky < 3; ky++) {
                #pragma unroll
                for (int kx = 0; kx < 3; kx++) {
                    float w = ws[(oc * 3 + i) * 9 + ky * 3 + kx];
                    a0 = fmaf(w, in[i][ky][kx],     a0);
                    a1 = fmaf(w, in[i][ky + 1][kx], a1);
                }
            }
        }
        a0 = 0.5f * a0 * (1.0f + erff(a0 * inv_sqrt2));
        a1 = 0.5f * a1 * (1.0f + erff(a1 * inv_sqrt2));
        size_t base = (((size_t)b * C1 + oc) * Hn + y0) * Wn + x;
        g_feat[base]      = a0;
        g_feat[base + Wn] = a1;
    }
}

// ---------------------------------------------------------------------------
// Bilinear sampling helpers
// ---------------------------------------------------------------------------
__device__ __forceinline__ float samp_point(const float* __restrict__ img,
                                            int yi, int xi) {
    bool valid = (yi >= 0) & (yi < Hn) & (xi >= 0) & (xi < Wn);
    int yc = min(max(yi, 0), Hn - 1);
    int xc = min(max(xi, 0), Wn - 1);
    float v = __ldg(img + yc * Wn + xc);
    return valid ? v : 0.0f;
}

__device__ __forceinline__ float bilinear(const float* __restrict__ img,
                                          float py, float px) {
    float fy = floorf(py), fx = floorf(px);
    float wy = py - fy,    wx = px - fx;
    int yi = (int)fy,      xi = (int)fx;
    float v00 = samp_point(img, yi,     xi);
    float v01 = samp_point(img, yi,     xi + 1);
    float v10 = samp_point(img, yi + 1, xi);
    float v11 = samp_point(img, yi + 1, xi + 1);
    float omy = 1.0f - wy, omx = 1.0f - wx;
    return v00 * omy * omx + v01 * omy * wx + v10 * wy * omx + v11 * wy * wx;
}

// ---------------------------------------------------------------------------
// Kernel 2 (fused, active-k): for each k with wk[k] != 0, compute ONLY the
// two conv2 channels (2k, 2k+1) it needs, then sample. 32x16 tile, 256 thr,
// 2 rows/thread, f32x2 FMA, dup-weight LDS.128.
// ---------------------------------------------------------------------------
__global__ __launch_bounds__(256, 3) void conv2_sample_kernel(
        const float* __restrict__ pm25,
        const float* __restrict__ w2,
        const float* __restrict__ b2,
        const float* __restrict__ wk,
        float* __restrict__ out) {
    extern __shared__ float smem[];
    float* sfeat = smem;                                // C1*PLANE
    float* swd   = sfeat + C1 * PLANE;                  // C1*C2*20 (dup taps)
    float* sb2   = swd + C1 * C2 * 20;                  // C2
    float* swk   = sb2 + C2;                            // 9

    int tid = threadIdx.x;                              // 256
    int bx0 = blockIdx.x * TW;
    int by0 = blockIdx.y * THY;
    int b   = blockIdx.z;

    // dup-weight staging: per (c,oc): taps 0..8 duplicated + pad (20 floats)
    for (int i = tid; i < C1 * C2 * 10; i += 256) {
        int t   = i % 10;
        int rem = i / 10;             // c*C2 + oc
        int oc  = rem % C2;
        int c   = rem / C2;
        float v = (t < 9) ? w2[(oc * C1 + c) * 9 + t] : 0.0f;
        swd[rem * 20 + 2 * t]     = v;
        swd[rem * 20 + 2 * t + 1] = v;
    }
    if (tid < C2) sb2[tid] = b2[tid];
    if (tid < 9)  swk[tid] = wk[tid];

    // feat tile load with zero halo
    {
        int yy0 = tid / HX;
        int xx0 = tid - yy0 * HX;
        #pragma unroll 1
        for (int c = 0; c < C1; c++) {
            const float* src = g_feat + ((size_t)b * C1 + c) * Hn * Wn;
            float* dst = sfeat + c * PLANE;
            int cyy = yy0, cxx = xx0;
            while (cyy < HY) {
                int gy = by0 + cyy - 1;
                int gx = bx0 + cxx - 1;
                float v = 0.0f;
                if ((unsigned)gy < Hn && (unsigned)gx < Wn)
                    v = __ldg(src + gy * Wn + gx);
                dst[cyy * HX + cxx] = v;
                cxx += 18; cyy += 7;                  // advance 256 = 7*34+18
                if (cxx >= HX) { cxx -= HX; cyy += 1; }
            }
        }
    }
    __syncthreads();

    int tx  = tid & 31;
    int r   = tid >> 5;
    int ylo = 2 * r;

    const float* img = pm25 + (size_t)b * Hn * Wn;
    int x = bx0 + tx;
    float ybase = (float)(by0 + ylo);
    float xf = (float)x;

    float o0 = 0.0f, o1 = 0.0f;

    // outer loop over kernel taps; skip inactive ones entirely (uniform branch)
    #pragma unroll 1
    for (int k = 0; k < 9; k++) {
        float wkv = swk[k];
        if (wkv == 0.0f) continue;
        int oc0 = 2 * k;
        int oc1 = 2 * k + 1;

        u64 accY = pack2(sb2[oc0], sb2[oc0]);   // dy channel
        u64 accX = pack2(sb2[oc1], sb2[oc1]);   // dx channel

        #pragma unroll 2
        for (int c = 0; c < C1; c++) {
            const float* fp = sfeat + c * PLANE + ylo * HX + tx;
            float fl[4][3];
            #pragma unroll
            for (int dy = 0; dy < 4; dy++)
                #pragma unroll
                for (int dx = 0; dx < 3; dx++)
                    fl[dy][dx] = fp[dy * HX + dx];

            u64 pA[9];
            #pragma unroll
            for (int ky = 0; ky < 3; ky++)
                #pragma unroll
                for (int kx = 0; kx < 3; kx++)
                    pA[ky * 3 + kx] = pack2(fl[ky][kx], fl[ky + 1][kx]);

            const float* wbY = swd + (c * C2 + oc0) * 20;
            const float* wbX = swd + (c * C2 + oc1) * 20;
            {
                const ulonglong2* wq = (const ulonglong2*)wbY;
                ulonglong2 q0 = wq[0], q1 = wq[1], q2 = wq[2], q3 = wq[3];
                u64 w8 = ((const u64*)wbY)[8];
                fma2(accY, q0.x, pA[0]); fma2(accY, q0.y, pA[1]);
                fma2(accY, q1.x, pA[2]); fma2(accY, q1.y, pA[3]);
                fma2(accY, q2.x, pA[4]); fma2(accY, q2.y, pA[5]);
                fma2(accY, q3.x, pA[6]); fma2(accY, q3.y, pA[7]);
                fma2(accY, w8,   pA[8]);
            }
            {
                const ulonglong2* wq = (const ulonglong2*)wbX;
                ulonglong2 q0 = wq[0], q1 = wq[1], q2 = wq[2], q3 = wq[3];
                u64 w8 = ((const u64*)wbX)[8];
                fma2(accX, q0.x, pA[0]); fma2(accX, q0.y, pA[1]);
                fma2(accX, q1.x, pA[2]); fma2(accX, q1.y, pA[3]);
                fma2(accX, q2.x, pA[4]); fma2(accX, q2.y, pA[5]);
                fma2(accX, q3.x, pA[6]); fma2(accX, q3.y, pA[7]);
                fma2(accX, w8,   pA[8]);
            }
        }

        float kdy = (float)(k / 3 - 1);
        float kdx = (float)(k % 3 - 1);
        float dy0, dy1, dx0, dx1;
        unpack2(accY, dy0, dy1);
        unpack2(accX, dx0, dx1);
        o0 = fmaf(wkv, bilinear(img, ybase + 0.0f + kdy + dy0, xf + kdx + dx0), o0);
        o1 = fmaf(wkv, bilinear(img, ybase + 1.0f + kdy + dy1, xf + kdx + dx1), o1);
    }

    size_t ob = ((size_t)b * Hn + (by0 + ylo)) * Wn + x;
    out[ob]      = o0;
    out[ob + Wn] = o1;
}

// ---------------------------------------------------------------------------
extern "C" void kernel_launch(void* const* d_in, const int* in_sizes, int n_in,
                              void* d_out, int out_size) {
    const float* pm25 = (const float*)d_in[0];
    const float* wind = (const float*)d_in[1];
    const float* topo = (const float*)d_in[2];
    const float* w1   = (const float*)d_in[3];
    const float* b1   = (const float*)d_in[4];
    const float* w2   = (const float*)d_in[5];
    const float* b2   = (const float*)d_in[6];
    const float* wk   = (const float*)d_in[7];
    float* out = (float*)d_out;

    // Kernel 1: conv1 + GELU
    int n1 = Bn * (Hn / 2) * Wn;
    conv1_gelu_kernel<<<n1 / 256, 256>>>(wind, topo, w1, b1);

    // Kernel 2: fused active-k conv2 + sampling
    int smemB = (C1 * PLANE + C1 * C2 * 20 + C2 + 9) * (int)sizeof(float);
    cudaFuncSetAttribute(conv2_sample_kernel,
                         cudaFuncAttributeMaxDynamicSharedMemorySize, smemB);
    dim3 grid(Wn / TW, Hn / THY, Bn);
    conv2_sample_kernel<<<grid, 256, smemB>>>(pm25, w2, b2, wk, out);
}

// round 6
// speedup vs baseline: 4.9504x; 1.8007x over previous
#include <cuda_runtime.h>
#include <math.h>

#define Bn 16
#define Hn 512
#define Wn 512
#define C1 16
#define C2 18
#define TW 32          // K2 tile width
#define THY 16         // K2 tile height
#define HX 34          // TW+2
#define HY 18          // THY+2
#define PLANE (HX*HY)  // 612

typedef unsigned long long u64;

// 256 MB scratch for conv1 output (B, C1, H, W)
__device__ float g_feat[(size_t)Bn * C1 * Hn * Wn];

// ---- f32x2 packed helpers (sm_100+) --------------------------------------
__device__ __forceinline__ u64 pack2(float lo, float hi) {
    u64 r;
    asm("mov.b64 %0, {%1, %2};" : "=l"(r) : "f"(lo), "f"(hi));
    return r;
}
__device__ __forceinline__ void unpack2(u64 v, float& lo, float& hi) {
    asm("mov.b64 {%0, %1}, %2;" : "=f"(lo), "=f"(hi) : "l"(v));
}
__device__ __forceinline__ void fma2(u64& d, u64 a, u64 b) {
    asm("fma.rn.f32x2 %0, %1, %2, %0;" : "+l"(d) : "l"(a), "l"(b));
}

// ---- cp.async 4B with zero-fill predication ------------------------------
__device__ __forceinline__ void cp_async4(unsigned smem_addr,
                                          const void* gptr, bool pred) {
    int sz = pred ? 4 : 0;
    asm volatile("cp.async.ca.shared.global [%0], [%1], 4, %2;"
                 :: "r"(smem_addr), "l"(gptr), "r"(sz) : "memory");
}

// ---------------------------------------------------------------------------
// Kernel 1: conv1 (3->16, 3x3, pad 1) + bias + exact GELU -> g_feat
// ---------------------------------------------------------------------------
__global__ void conv1_gelu_kernel(const float* __restrict__ wind,
                                  const float* __restrict__ topo,
                                  const float* __restrict__ w1,
                                  const float* __restrict__ b1) {
    __shared__ float ws[C1 * 27];
    __shared__ float bs[C1];
    int tid = threadIdx.x;
    for (int i = tid; i < C1 * 27; i += blockDim.x) ws[i] = w1[i];
    if (tid < C1) bs[tid] = b1[tid];
    __syncthreads();

    int idx = blockIdx.x * blockDim.x + tid;      // [0, B*(H/2)*W)
    int x  = idx % Wn;
    int r  = idx / Wn;
    int y0 = (r % (Hn / 2)) * 2;
    int b  = r / (Hn / 2);

    const float* chp[3] = {
        wind + ((size_t)b * 2 + 0) * Hn * Wn,
        wind + ((size_t)b * 2 + 1) * Hn * Wn,
        topo + (size_t)b * Hn * Wn
    };

    float in[3][4][3];
    #pragma unroll
    for (int i = 0; i < 3; i++) {
        #pragma unroll
        for (int yy = 0; yy < 4; yy++) {
            int gy = y0 - 1 + yy;
            #pragma unroll
            for (int xx = 0; xx < 3; xx++) {
                int gx = x - 1 + xx;
                float v = 0.0f;
                if (gy >= 0 && gy < Hn && gx >= 0 && gx < Wn)
                    v = __ldg(chp[i] + gy * Wn + gx);
                in[i][yy][xx] = v;
            }
        }
    }

    const float inv_sqrt2 = 0.70710678118654752440f;
    #pragma unroll
    for (int oc = 0; oc < C1; oc++) {
        float a0 = bs[oc], a1 = a0;
        #pragma unroll
        for (int i = 0; i < 3; i++) {
            #pragma unroll
            for (int ky = 0; ky < 3; ky++) {
                #pragma unroll
                for (int kx = 0; kx < 3; kx++) {
                    float w = ws[(oc * 3 + i) * 9 + ky * 3 + kx];
                    a0 = fmaf(w, in[i][ky][kx],     a0);
                    a1 = fmaf(w, in[i][ky + 1][kx], a1);
                }
            }
        }
        a0 = 0.5f * a0 * (1.0f + erff(a0 * inv_sqrt2));
        a1 = 0.5f * a1 * (1.0f + erff(a1 * inv_sqrt2));
        size_t base = (((size_t)b * C1 + oc) * Hn + y0) * Wn + x;
        g_feat[base]      = a0;
        g_feat[base + Wn] = a1;
    }
}

// ---------------------------------------------------------------------------
// Bilinear sampling helpers
// ---------------------------------------------------------------------------
__device__ __forceinline__ float samp_point(const float* __restrict__ img,
                                            int yi, int xi) {
    bool valid = (yi >= 0) & (yi < Hn) & (xi >= 0) & (xi < Wn);
    int yc = min(max(yi, 0), Hn - 1);
    int xc = min(max(xi, 0), Wn - 1);
    float v = __ldg(img + yc * Wn + xc);
    return valid ? v : 0.0f;
}

__device__ __forceinline__ float bilinear(const float* __restrict__ img,
                                          float py, float px) {
    float fy = floorf(py), fx = floorf(px);
    float wy = py - fy,    wx = px - fx;
    int yi = (int)fy,      xi = (int)fx;
    float v00 = samp_point(img, yi,     xi);
    float v01 = samp_point(img, yi,     xi + 1);
    float v10 = samp_point(img, yi + 1, xi);
    float v11 = samp_point(img, yi + 1, xi + 1);
    float omy = 1.0f - wy, omx = 1.0f - wx;
    return v00 * omy * omx + v01 * omy * wx + v10 * wy * omx + v11 * wy * wx;
}

// ---------------------------------------------------------------------------
// Kernel 2 (fused, active-k, cp.async tile load)
// ---------------------------------------------------------------------------
__global__ __launch_bounds__(256, 3) void conv2_sample_kernel(
        const float* __restrict__ pm25,
        const float* __restrict__ w2,
        const float* __restrict__ b2,
        const float* __restrict__ wk,
        float* __restrict__ out) {
    extern __shared__ float smem[];
    float* sfeat = smem;                                // C1*PLANE
    float* swd   = sfeat + C1 * PLANE;                  // C1*C2*20 (dup taps)
    float* sb2   = swd + C1 * C2 * 20;                  // C2
    float* swk   = sb2 + C2;                            // 9

    int tid = threadIdx.x;                              // 256
    int bx0 = blockIdx.x * TW;
    int by0 = blockIdx.y * THY;
    int b   = blockIdx.z;

    // ---- issue all feat-tile cp.asyncs first (48 per thread, zero-fill halo)
    {
        unsigned sfeat_s = (unsigned)__cvta_generic_to_shared(sfeat);
        const float* src0 = g_feat + (size_t)b * C1 * Hn * Wn;
        #pragma unroll
        for (int j = 0; j < 3; j++) {
            int idx = tid + j * 256;
            if (idx < PLANE) {
                int yy = idx / HX;
                int xx = idx - yy * HX;
                int gy = by0 + yy - 1;
                int gx = bx0 + xx - 1;
                bool ok = ((unsigned)gy < Hn) & ((unsigned)gx < Wn);
                int gyc = min(max(gy, 0), Hn - 1);
                int gxc = min(max(gx, 0), Wn - 1);
                size_t off = (size_t)gyc * Wn + gxc;
                #pragma unroll
                for (int c = 0; c < C1; c++)
                    cp_async4(sfeat_s + (unsigned)((c * PLANE + idx) * 4),
                              src0 + (size_t)c * Hn * Wn + off, ok);
            }
        }
    }

    // ---- weight staging runs while cp.asyncs are in flight ----
    for (int i = tid; i < C1 * C2 * 10; i += 256) {
        int t   = i % 10;
        int rem = i / 10;             // c*C2 + oc
        int oc  = rem % C2;
        int c   = rem / C2;
        float v = (t < 9) ? w2[(oc * C1 + c) * 9 + t] : 0.0f;
        swd[rem * 20 + 2 * t]     = v;
        swd[rem * 20 + 2 * t + 1] = v;
    }
    if (tid < C2) sb2[tid] = b2[tid];
    if (tid < 9)  swk[tid] = wk[tid];

    asm volatile("cp.async.commit_group;" ::: "memory");
    asm volatile("cp.async.wait_group 0;" ::: "memory");
    __syncthreads();

    int tx  = tid & 31;
    int r   = tid >> 5;
    int ylo = 2 * r;

    const float* img = pm25 + (size_t)b * Hn * Wn;
    int x = bx0 + tx;
    float ybase = (float)(by0 + ylo);
    float xf = (float)x;

    float o0 = 0.0f, o1 = 0.0f;

    // outer loop over kernel taps; skip inactive ones entirely (uniform branch)
    #pragma unroll 1
    for (int k = 0; k < 9; k++) {
        float wkv = swk[k];
        if (wkv == 0.0f) continue;
        int oc0 = 2 * k;
        int oc1 = 2 * k + 1;

        u64 accY = pack2(sb2[oc0], sb2[oc0]);   // dy channel
        u64 accX = pack2(sb2[oc1], sb2[oc1]);   // dx channel

        #pragma unroll 2
        for (int c = 0; c < C1; c++) {
            const float* fp = sfeat + c * PLANE + ylo * HX + tx;
            float fl[4][3];
            #pragma unroll
            for (int dy = 0; dy < 4; dy++)
                #pragma unroll
                for (int dx = 0; dx < 3; dx++)
                    fl[dy][dx] = fp[dy * HX + dx];

            u64 pA[9];
            #pragma unroll
            for (int ky = 0; ky < 3; ky++)
                #pragma unroll
                for (int kx = 0; kx < 3; kx++)
                    pA[ky * 3 + kx] = pack2(fl[ky][kx], fl[ky + 1][kx]);

            const float* wbY = swd + (c * C2 + oc0) * 20;
            const float* wbX = swd + (c * C2 + oc1) * 20;
            {
                const ulonglong2* wq = (const ulonglong2*)wbY;
                ulonglong2 q0 = wq[0], q1 = wq[1], q2 = wq[2], q3 = wq[3];
                u64 w8 = ((const u64*)wbY)[8];
                fma2(accY, q0.x, pA[0]); fma2(accY, q0.y, pA[1]);
                fma2(accY, q1.x, pA[2]); fma2(accY, q1.y, pA[3]);
                fma2(accY, q2.x, pA[4]); fma2(accY, q2.y, pA[5]);
                fma2(accY, q3.x, pA[6]); fma2(accY, q3.y, pA[7]);
                fma2(accY, w8,   pA[8]);
            }
            {
                const ulonglong2* wq = (const ulonglong2*)wbX;
                ulonglong2 q0 = wq[0], q1 = wq[1], q2 = wq[2], q3 = wq[3];
                u64 w8 = ((const u64*)wbX)[8];
                fma2(accX, q0.x, pA[0]); fma2(accX, q0.y, pA[1]);
                fma2(accX, q1.x, pA[2]); fma2(accX, q1.y, pA[3]);
                fma2(accX, q2.x, pA[4]); fma2(accX, q2.y, pA[5]);
                fma2(accX, q3.x, pA[6]); fma2(accX, q3.y, pA[7]);
                fma2(accX, w8,   pA[8]);
            }
        }

        float kdy = (float)(k / 3 - 1);
        float kdx = (float)(k % 3 - 1);
        float dy0, dy1, dx0, dx1;
        unpack2(accY, dy0, dy1);
        unpack2(accX, dx0, dx1);
        o0 = fmaf(wkv, bilinear(img, ybase + 0.0f + kdy + dy0, xf + kdx + dx0), o0);
        o1 = fmaf(wkv, bilinear(img, ybase + 1.0f + kdy + dy1, xf + kdx + dx1), o1);
    }

    size_t ob = ((size_t)b * Hn + (by0 + ylo)) * Wn + x;
    out[ob]      = o0;
    out[ob + Wn] = o1;
}

// ---------------------------------------------------------------------------
extern "C" void kernel_launch(void* const* d_in, const int* in_sizes, int n_in,
                              void* d_out, int out_size) {
    const float* pm25 = (const float*)d_in[0];
    const float* wind = (const float*)d_in[1];
    const float* topo = (const float*)d_in[2];
    const float* w1   = (const float*)d_in[3];
    const float* b1   = (const float*)d_in[4];
    const float* w2   = (const float*)d_in[5];
    const float* b2   = (const float*)d_in[6];
    const float* wk   = (const float*)d_in[7];
    float* out = (float*)d_out;

    // Kernel 1: conv1 + GELU
    int n1 = Bn * (Hn / 2) * Wn;
    conv1_gelu_kernel<<<n1 / 256, 256>>>(wind, topo, w1, b1);

    // Kernel 2: fused active-k conv2 + sampling, cp.async tile load
    int smemB = (C1 * PLANE + C1 * C2 * 20 + C2 + 9) * (int)sizeof(float);
    cudaFuncSetAttribute(conv2_sample_kernel,
                         cudaFuncAttributeMaxDynamicSharedMemorySize, smemB);
    dim3 grid(Wn / TW, Hn / THY, Bn);
    conv2_sample_kernel<<<grid, 256, smemB>>>(pm25, w2, b2, wk, out);
}

// round 7
// speedup vs baseline: 7.0270x; 1.4195x over previous
#include <cuda_runtime.h>
#include <math.h>

#define Bn 16
#define Hn 512
#define Wn 512
#define C1 16
#define C2 18
#define TW 32          // K2 tile width
#define THY 16         // K2 tile height
#define HY 18          // THY+2 rows
#define W2R 40         // smem row stride (floats): cols cover gx in [bx0-4, bx0+36)
#define CPLANE (HY*W2R)          // 720 floats per channel
#define NCHUNK (C1*HY*10)        // 2880 16B-chunks per block

// 256 MB scratch for conv1 output (B, C1, H, W)
__device__ float g_feat[(size_t)Bn * C1 * Hn * Wn];

// conv weights in constant memory (uniform access -> LDCU/UR, no smem traffic)
__constant__ float c_w1[C1 * 27];
__constant__ float c_b1[C1];
__constant__ float c_w2[C2 * C1 * 9];
__constant__ float c_b2[C2];
__constant__ float c_wk[9];

// ---- cp.async 16B with full-chunk zero-fill predication ------------------
__device__ __forceinline__ void cp_async16(unsigned smem_addr,
                                           const void* gptr, bool pred) {
    int sz = pred ? 16 : 0;
    asm volatile("cp.async.cg.shared.global [%0], [%1], 16, %2;"
                 :: "r"(smem_addr), "l"(gptr), "r"(sz) : "memory");
}

// ---------------------------------------------------------------------------
// Kernel 1: conv1 (3->16, 3x3, pad 1) + bias + exact GELU -> g_feat
// Weights from constant memory; no smem, no syncthreads.
// ---------------------------------------------------------------------------
__global__ void conv1_gelu_kernel(const float* __restrict__ wind,
                                  const float* __restrict__ topo) {
    int tid = threadIdx.x;
    int idx = blockIdx.x * blockDim.x + tid;      // [0, B*(H/2)*W)
    int x  = idx % Wn;
    int r  = idx / Wn;
    int y0 = (r % (Hn / 2)) * 2;
    int b  = r / (Hn / 2);

    const float* chp[3] = {
        wind + ((size_t)b * 2 + 0) * Hn * Wn,
        wind + ((size_t)b * 2 + 1) * Hn * Wn,
        topo + (size_t)b * Hn * Wn
    };

    float in[3][4][3];
    #pragma unroll
    for (int i = 0; i < 3; i++) {
        #pragma unroll
        for (int yy = 0; yy < 4; yy++) {
            int gy = y0 - 1 + yy;
            #pragma unroll
            for (int xx = 0; xx < 3; xx++) {
                int gx = x - 1 + xx;
                float v = 0.0f;
                if (gy >= 0 && gy < Hn && gx >= 0 && gx < Wn)
                    v = __ldg(chp[i] + gy * Wn + gx);
                in[i][yy][xx] = v;
            }
        }
    }

    const float inv_sqrt2 = 0.70710678118654752440f;
    #pragma unroll
    for (int oc = 0; oc < C1; oc++) {
        float a0 = c_b1[oc], a1 = a0;
        #pragma unroll
        for (int i = 0; i < 3; i++) {
            #pragma unroll
            for (int ky = 0; ky < 3; ky++) {
                #pragma unroll
                for (int kx = 0; kx < 3; kx++) {
                    float w = c_w1[(oc * 3 + i) * 9 + ky * 3 + kx];
                    a0 = fmaf(w, in[i][ky][kx],     a0);
                    a1 = fmaf(w, in[i][ky + 1][kx], a1);
                }
            }
        }
        a0 = 0.5f * a0 * (1.0f + erff(a0 * inv_sqrt2));
        a1 = 0.5f * a1 * (1.0f + erff(a1 * inv_sqrt2));
        size_t base = (((size_t)b * C1 + oc) * Hn + y0) * Wn + x;
        g_feat[base]      = a0;
        g_feat[base + Wn] = a1;
    }
}

// ---------------------------------------------------------------------------
// Bilinear sampling helpers
// ---------------------------------------------------------------------------
__device__ __forceinline__ float samp_point(const float* __restrict__ img,
                                            int yi, int xi) {
    bool valid = (yi >= 0) & (yi < Hn) & (xi >= 0) & (xi < Wn);
    int yc = min(max(yi, 0), Hn - 1);
    int xc = min(max(xi, 0), Wn - 1);
    float v = __ldg(img + yc * Wn + xc);
    return valid ? v : 0.0f;
}

__device__ __forceinline__ float bilinear(const float* __restrict__ img,
                                          float py, float px) {
    float fy = floorf(py), fx = floorf(px);
    float wy = py - fy,    wx = px - fx;
    int yi = (int)fy,      xi = (int)fx;
    float v00 = samp_point(img, yi,     xi);
    float v01 = samp_point(img, yi,     xi + 1);
    float v10 = samp_point(img, yi + 1, xi);
    float v11 = samp_point(img, yi + 1, xi + 1);
    float omy = 1.0f - wy, omx = 1.0f - wx;
    return v00 * omy * omx + v01 * omy * wx + v10 * wy * omx + v11 * wy * wx;
}

// ---------------------------------------------------------------------------
// Kernel 2 (fused, active-k): conv2 channels (2k, 2k+1) only for wk[k]!=0,
// then bilinear sampling. Weights/bias/wk from constant memory. Feature tile
// via 16B cp.async into 40-float-stride smem (all chunks fully valid or
// fully zero-filled). 256 threads, 32x16 tile, 2 rows/thread, 4 blocks/SM.
// ---------------------------------------------------------------------------
__global__ __launch_bounds__(256, 4) void conv2_sample_kernel(
        const float* __restrict__ pm25,
        float* __restrict__ out) {
    extern __shared__ float sfeat[];                 // C1 * CPLANE floats

    int tid = threadIdx.x;                           // 256
    int bx0 = blockIdx.x * TW;
    int by0 = blockIdx.y * THY;
    int b   = blockIdx.z;

    // ---- issue all feat-tile cp.asyncs (16B chunks, zero-fill OOB) ----
    {
        unsigned sbase = (unsigned)__cvta_generic_to_shared(sfeat);
        const float* src0 = g_feat + (size_t)b * C1 * Hn * Wn;
        #pragma unroll
        for (int m = 0; m < 12; m++) {
            int idx = tid + m * 256;
            if (idx < NCHUNK) {
                int j  = idx % 10;                   // chunk within row
                int rc = idx / 10;
                int yy = rc % HY;
                int c  = rc / HY;
                int gy  = by0 + yy - 1;
                int gx0 = bx0 - 4 + 4 * j;
                bool ok = ((unsigned)gy < Hn) & ((unsigned)gx0 < Wn);
                int gyc = min(max(gy, 0), Hn - 1);
                int gxc = ok ? gx0 : 0;
                cp_async16(sbase + (unsigned)((c * CPLANE + yy * W2R + 4 * j) * 4),
                           src0 + (size_t)c * Hn * Wn + (size_t)gyc * Wn + gxc, ok);
            }
        }
        asm volatile("cp.async.commit_group;" ::: "memory");
        asm volatile("cp.async.wait_group 0;" ::: "memory");
    }
    __syncthreads();

    int tx  = tid & 31;
    int r   = tid >> 5;
    int ylo = 2 * r;

    const float* img = pm25 + (size_t)b * Hn * Wn;
    int x = bx0 + tx;
    float ybase = (float)(by0 + ylo);
    float xf = (float)x;

    float o0 = 0.0f, o1 = 0.0f;

    // outer loop over kernel taps; skip inactive ones (uniform branch)
    #pragma unroll 1
    for (int k = 0; k < 9; k++) {
        float wkv = c_wk[k];
        if (wkv == 0.0f) continue;
        int oc0 = 2 * k;
        int oc1 = 2 * k + 1;

        float aY0 = c_b2[oc0], aY1 = aY0;   // dy channel, rows ylo / ylo+1
        float aX0 = c_b2[oc1], aX1 = aX0;   // dx channel

        #pragma unroll 4
        for (int c = 0; c < C1; c++) {
            // tile-local col for gx = bx0+tx-1+kx is (tx+3+kx) in 40-stride rows
            const float* fp = sfeat + c * CPLANE + ylo * W2R + tx + 3;
            float fl[4][3];
            #pragma unroll
            for (int dy = 0; dy < 4; dy++)
                #pragma unroll
                for (int dx = 0; dx < 3; dx++)
                    fl[dy][dx] = fp[dy * W2R + dx];

            const float* wY = c_w2 + (oc0 * C1 + c) * 9;
            const float* wX = c_w2 + (oc1 * C1 + c) * 9;
            #pragma unroll
            for (int ky = 0; ky < 3; ky++)
                #pragma unroll
                for (int kx = 0; kx < 3; kx++) {
                    int t = ky * 3 + kx;
                    float vy = wY[t], vx = wX[t];
                    aY0 = fmaf(vy, fl[ky][kx],     aY0);
                    aY1 = fmaf(vy, fl[ky + 1][kx], aY1);
                    aX0 = fmaf(vx, fl[ky][kx],     aX0);
                    aX1 = fmaf(vx, fl[ky + 1][kx], aX1);
                }
        }

        float kdy = (float)(k / 3 - 1);
        float kdx = (float)(k % 3 - 1);
        o0 = fmaf(wkv, bilinear(img, ybase + 0.0f + kdy + aY0, xf + kdx + aX0), o0);
        o1 = fmaf(wkv, bilinear(img, ybase + 1.0f + kdy + aY1, xf + kdx + aX1), o1);
    }

    size_t ob = ((size_t)b * Hn + (by0 + ylo)) * Wn + x;
    out[ob]      = o0;
    out[ob + Wn] = o1;
}

// ---------------------------------------------------------------------------
extern "C" void kernel_launch(void* const* d_in, const int* in_sizes, int n_in,
                              void* d_out, int out_size) {
    const float* pm25 = (const float*)d_in[0];
    const float* wind = (const float*)d_in[1];
    const float* topo = (const float*)d_in[2];
    const float* w1   = (const float*)d_in[3];
    const float* b1   = (const float*)d_in[4];
    const float* w2   = (const float*)d_in[5];
    const float* b2   = (const float*)d_in[6];
    const float* wk   = (const float*)d_in[7];
    float* out = (float*)d_out;

    // Stage weights into constant memory (async D2D copies; graph-capturable)
    cudaMemcpyToSymbolAsync(c_w1, w1, C1 * 27 * sizeof(float), 0,
                            cudaMemcpyDeviceToDevice, 0);
    cudaMemcpyToSymbolAsync(c_b1, b1, C1 * sizeof(float), 0,
                            cudaMemcpyDeviceToDevice, 0);
    cudaMemcpyToSymbolAsync(c_w2, w2, C2 * C1 * 9 * sizeof(float), 0,
                            cudaMemcpyDeviceToDevice, 0);
    cudaMemcpyToSymbolAsync(c_b2, b2, C2 * sizeof(float), 0,
                            cudaMemcpyDeviceToDevice, 0);
    cudaMemcpyToSymbolAsync(c_wk, wk, 9 * sizeof(float), 0,
                            cudaMemcpyDeviceToDevice, 0);

    // Kernel 1: conv1 + GELU
    int n1 = Bn * (Hn / 2) * Wn;
    conv1_gelu_kernel<<<n1 / 256, 256>>>(wind, topo);

    // Kernel 2: fused active-k conv2 + sampling
    int smemB = C1 * CPLANE * (int)sizeof(float);    // 46080 B
    cudaFuncSetAttribute(conv2_sample_kernel,
                         cudaFuncAttributeMaxDynamicSharedMemorySize, smemB);
    dim3 grid(Wn / TW, Hn / THY, Bn);
    conv2_sample_kernel<<<grid, 256, smemB>>>(pm25, out);
}

// round 8
// speedup vs baseline: 7.1375x; 1.0157x over previous
#include <cuda_runtime.h>
#include <math.h>

#define Bn 16
#define Hn 512
#define Wn 512
#define C1 16
#define C2 18
#define TW 32          // K2 tile width
#define THY 16         // K2 tile height
#define HY 18          // THY+2 rows
#define W2R 40         // K2 smem row stride (floats)
#define CPLANE (HY*W2R)          // 720 floats per channel
#define NCHUNK (C1*HY*10)        // 2880 16B-chunks per block

typedef unsigned long long u64;

// 256 MB scratch for conv1 output (B, C1, H, W)
__device__ float g_feat[(size_t)Bn * C1 * Hn * Wn];

// conv weights in constant memory (uniform access, no smem traffic)
__constant__ float c_w1[C1 * 27];
__constant__ float c_b1[C1];
__constant__ float c_w2[C2 * C1 * 9];
__constant__ float c_b2[C2];
__constant__ float c_wk[9];

// ---- f32x2 packed helpers (sm_100+) --------------------------------------
__device__ __forceinline__ u64 pack2(float lo, float hi) {
    u64 r;
    asm("mov.b64 %0, {%1, %2};" : "=l"(r) : "f"(lo), "f"(hi));
    return r;
}
__device__ __forceinline__ void unpack2(u64 v, float& lo, float& hi) {
    asm("mov.b64 {%0, %1}, %2;" : "=f"(lo), "=f"(hi) : "l"(v));
}
__device__ __forceinline__ void fma2(u64& d, u64 a, u64 b) {
    asm("fma.rn.f32x2 %0, %1, %2, %0;" : "+l"(d) : "l"(a), "l"(b));
}

// ---- cp.async 16B with full-chunk zero-fill predication ------------------
__device__ __forceinline__ void cp_async16(unsigned smem_addr,
                                           const void* gptr, bool pred) {
    int sz = pred ? 16 : 0;
    asm volatile("cp.async.cg.shared.global [%0], [%1], 16, %2;"
                 :: "r"(smem_addr), "l"(gptr), "r"(sz) : "memory");
}

// ---------------------------------------------------------------------------
// Kernel 1: conv1 (3->16, 3x3, pad 1) + bias + exact GELU -> g_feat
// Horizontal pixel pair per thread, f32x2 packed conv, const-mem weights,
// STG.64 output stores.
// ---------------------------------------------------------------------------
__global__ __launch_bounds__(256, 3) void conv1_gelu_kernel(
        const float* __restrict__ wind,
        const float* __restrict__ topo) {
    int tid = threadIdx.x;
    int idx = blockIdx.x * blockDim.x + tid;      // [0, B*H*(W/2))
    int xh = idx & 255;                           // W/2 = 256
    int x0 = xh << 1;                             // even column
    int r  = idx >> 8;
    int y  = r & (Hn - 1);
    int b  = r >> 9;

    const float* chp[3] = {
        wind + ((size_t)b * 2 + 0) * Hn * Wn,
        wind + ((size_t)b * 2 + 1) * Hn * Wn,
        topo + (size_t)b * Hn * Wn
    };

    // input rows y-1..y+1, cols x0-1..x0+2, 3 channels
    float in[3][3][4];
    #pragma unroll
    for (int c = 0; c < 3; c++) {
        #pragma unroll
        for (int ky = 0; ky < 3; ky++) {
            int gy = y - 1 + ky;
            #pragma unroll
            for (int kx = 0; kx < 4; kx++) {
                int gx = x0 - 1 + kx;
                float v = 0.0f;
                if ((unsigned)gy < Hn && (unsigned)gx < Wn)
                    v = __ldg(chp[c] + gy * Wn + gx);
                in[c][ky][kx] = v;
            }
        }
    }

    // packed horizontal pairs: p[c][ky][kx] covers outputs (x0, x0+1)
    u64 p[3][3][3];
    #pragma unroll
    for (int c = 0; c < 3; c++)
        #pragma unroll
        for (int ky = 0; ky < 3; ky++)
            #pragma unroll
            for (int kx = 0; kx < 3; kx++)
                p[c][ky][kx] = pack2(in[c][ky][kx], in[c][ky][kx + 1]);

    const float inv_sqrt2 = 0.70710678118654752440f;
    #pragma unroll
    for (int oc = 0; oc < C1; oc++) {
        float bb = c_b1[oc];
        u64 acc = pack2(bb, bb);
        const float* w = c_w1 + oc * 27;
        #pragma unroll
        for (int c = 0; c < 3; c++)
            #pragma unroll
            for (int ky = 0; ky < 3; ky++)
                #pragma unroll
                for (int kx = 0; kx < 3; kx++) {
                    float wv = w[c * 9 + ky * 3 + kx];
                    fma2(acc, pack2(wv, wv), p[c][ky][kx]);
                }
        float a0, a1;
        unpack2(acc, a0, a1);
        a0 = 0.5f * a0 * (1.0f + erff(a0 * inv_sqrt2));
        a1 = 0.5f * a1 * (1.0f + erff(a1 * inv_sqrt2));
        float2 o = make_float2(a0, a1);
        *(float2*)(g_feat + (((size_t)b * C1 + oc) * Hn + y) * Wn + x0) = o;
    }
}

// ---------------------------------------------------------------------------
// Bilinear sampling helpers
// ---------------------------------------------------------------------------
__device__ __forceinline__ float samp_point(const float* __restrict__ img,
                                            int yi, int xi) {
    bool valid = (yi >= 0) & (yi < Hn) & (xi >= 0) & (xi < Wn);
    int yc = min(max(yi, 0), Hn - 1);
    int xc = min(max(xi, 0), Wn - 1);
    float v = __ldg(img + yc * Wn + xc);
    return valid ? v : 0.0f;
}

__device__ __forceinline__ float bilinear(const float* __restrict__ img,
                                          float py, float px) {
    float fy = floorf(py), fx = floorf(px);
    float wy = py - fy,    wx = px - fx;
    int yi = (int)fy,      xi = (int)fx;
    float v00 = samp_point(img, yi,     xi);
    float v01 = samp_point(img, yi,     xi + 1);
    float v10 = samp_point(img, yi + 1, xi);
    float v11 = samp_point(img, yi + 1, xi + 1);
    float omy = 1.0f - wy, omx = 1.0f - wx;
    return v00 * omy * omx + v01 * omy * wx + v10 * wy * omx + v11 * wy * wx;
}

// ---------------------------------------------------------------------------
// Kernel 2 (unchanged from R7): fused active-k conv2 + sampling.
// ---------------------------------------------------------------------------
__global__ __launch_bounds__(256, 4) void conv2_sample_kernel(
        const float* __restrict__ pm25,
        float* __restrict__ out) {
    extern __shared__ float sfeat[];                 // C1 * CPLANE floats

    int tid = threadIdx.x;                           // 256
    int bx0 = blockIdx.x * TW;
    int by0 = blockIdx.y * THY;
    int b   = blockIdx.z;

    // ---- issue all feat-tile cp.asyncs (16B chunks, zero-fill OOB) ----
    {
        unsigned sbase = (unsigned)__cvta_generic_to_shared(sfeat);
        const float* src0 = g_feat + (size_t)b * C1 * Hn * Wn;
        #pragma unroll
        for (int m = 0; m < 12; m++) {
            int idx = tid + m * 256;
            if (idx < NCHUNK) {
                int j  = idx % 10;                   // chunk within row
                int rc = idx / 10;
                int yy = rc % HY;
                int c  = rc / HY;
                int gy  = by0 + yy - 1;
                int gx0 = bx0 - 4 + 4 * j;
                bool ok = ((unsigned)gy < Hn) & ((unsigned)gx0 < Wn);
                int gyc = min(max(gy, 0), Hn - 1);
                int gxc = ok ? gx0 : 0;
                cp_async16(sbase + (unsigned)((c * CPLANE + yy * W2R + 4 * j) * 4),
                           src0 + (size_t)c * Hn * Wn + (size_t)gyc * Wn + gxc, ok);
            }
        }
        asm volatile("cp.async.commit_group;" ::: "memory");
        asm volatile("cp.async.wait_group 0;" ::: "memory");
    }
    __syncthreads();

    int tx  = tid & 31;
    int r   = tid >> 5;
    int ylo = 2 * r;

    const float* img = pm25 + (size_t)b * Hn * Wn;
    int x = bx0 + tx;
    float ybase = (float)(by0 + ylo);
    float xf = (float)x;

    float o0 = 0.0f, o1 = 0.0f;

    #pragma unroll 1
    for (int k = 0; k < 9; k++) {
        float wkv = c_wk[k];
        if (wkv == 0.0f) continue;
        int oc0 = 2 * k;
        int oc1 = 2 * k + 1;

        float aY0 = c_b2[oc0], aY1 = aY0;
        float aX0 = c_b2[oc1], aX1 = aX0;

        #pragma unroll 4
        for (int c = 0; c < C1; c++) {
            const float* fp = sfeat + c * CPLANE + ylo * W2R + tx + 3;
            float fl[4][3];
            #pragma unroll
            for (int dy = 0; dy < 4; dy++)
                #pragma unroll
                for (int dx = 0; dx < 3; dx++)
                    fl[dy][dx] = fp[dy * W2R + dx];

            const float* wY = c_w2 + (oc0 * C1 + c) * 9;
            const float* wX = c_w2 + (oc1 * C1 + c) * 9;
            #pragma unroll
            for (int ky = 0; ky < 3; ky++)
                #pragma unroll
                for (int kx = 0; kx < 3; kx++) {
                    int t = ky * 3 + kx;
                    float vy = wY[t], vx = wX[t];
                    aY0 = fmaf(vy, fl[ky][kx],     aY0);
                    aY1 = fmaf(vy, fl[ky + 1][kx], aY1);
                    aX0 = fmaf(vx, fl[ky][kx],     aX0);
                    aX1 = fmaf(vx, fl[ky + 1][kx], aX1);
                }
        }

        float kdy = (float)(k / 3 - 1);
        float kdx = (float)(k % 3 - 1);
        o0 = fmaf(wkv, bilinear(img, ybase + 0.0f + kdy + aY0, xf + kdx + aX0), o0);
        o1 = fmaf(wkv, bilinear(img, ybase + 1.0f + kdy + aY1, xf + kdx + aX1), o1);
    }

    size_t ob = ((size_t)b * Hn + (by0 + ylo)) * Wn + x;
    out[ob]      = o0;
    out[ob + Wn] = o1;
}

// ---------------------------------------------------------------------------
extern "C" void kernel_launch(void* const* d_in, const int* in_sizes, int n_in,
                              void* d_out, int out_size) {
    const float* pm25 = (const float*)d_in[0];
    const float* wind = (const float*)d_in[1];
    const float* topo = (const float*)d_in[2];
    const float* w1   = (const float*)d_in[3];
    const float* b1   = (const float*)d_in[4];
    const float* w2   = (const float*)d_in[5];
    const float* b2   = (const float*)d_in[6];
    const float* wk   = (const float*)d_in[7];
    float* out = (float*)d_out;

    // Stage weights into constant memory (async D2D copies; graph-capturable)
    cudaMemcpyToSymbolAsync(c_w1, w1, C1 * 27 * sizeof(float), 0,
                            cudaMemcpyDeviceToDevice, 0);
    cudaMemcpyToSymbolAsync(c_b1, b1, C1 * sizeof(float), 0,
                            cudaMemcpyDeviceToDevice, 0);
    cudaMemcpyToSymbolAsync(c_w2, w2, C2 * C1 * 9 * sizeof(float), 0,
                            cudaMemcpyDeviceToDevice, 0);
    cudaMemcpyToSymbolAsync(c_b2, b2, C2 * sizeof(float), 0,
                            cudaMemcpyDeviceToDevice, 0);
    cudaMemcpyToSymbolAsync(c_wk, wk, 9 * sizeof(float), 0,
                            cudaMemcpyDeviceToDevice, 0);

    // Kernel 1: conv1 + GELU (horizontal pairs)
    int n1 = Bn * Hn * (Wn / 2);                  // 2,097,152 threads
    conv1_gelu_kernel<<<n1 / 256, 256>>>(wind, topo);

    // Kernel 2: fused active-k conv2 + sampling
    int smemB = C1 * CPLANE * (int)sizeof(float);    // 46080 B
    cudaFuncSetAttribute(conv2_sample_kernel,
                         cudaFuncAttributeMaxDynamicSharedMemorySize, smemB);
    dim3 grid(Wn / TW, Hn / THY, Bn);
    conv2_sample_kernel<<<grid, 256, smemB>>>(pm25, out);
}